// round 12
// baseline (speedup 1.0000x reference)
#include <cuda_runtime.h>
#include <cuda_fp16.h>
#include <math.h>
#include <stdint.h>

// Problem dims (fixed by the dataset)
#define BB    2
#define LL    1024
#define NN    8
#define EE    512
#define HH    8
#define HD    64
#define E3    1536
#define MTOK  (BB * LL * NN)          // 16384 tokens

// ---------------------------------------------------------------------------
// Scratch (device globals)
// ---------------------------------------------------------------------------
__device__ half  g_qkv [(size_t)MTOK * 1024];        // [token][1024] q|k post-RoPE
__device__ half  g_v   [(size_t)BB * NN * HH * HD * LL]; // [bnh][d][L] V transposed
__device__ half  g_y   [(size_t)MTOK * EE];          // attention out
__device__ float g_rope[(size_t)BB * LL * 64];       // [b*L+l][cos32|sin32]
__device__ half  g_x   [(size_t)MTOK * EE];          // x fp16
__device__ half  g_wa  [(size_t)E3 * EE];            // w_attn^T  [n][k] fp16
__device__ half  g_wp  [(size_t)EE * EE];            // w_proj^T  [n][k] fp16

// ---------------------------------------------------------------------------
// helpers
// ---------------------------------------------------------------------------
__device__ __forceinline__ void mma_f16(float* c, const uint32_t* a,
                                        const uint32_t* b) {
    asm volatile(
        "mma.sync.aligned.m16n8k16.row.col.f32.f16.f16.f32 "
        "{%0,%1,%2,%3}, {%4,%5,%6,%7}, {%8,%9}, {%0,%1,%2,%3};"
        : "+f"(c[0]), "+f"(c[1]), "+f"(c[2]), "+f"(c[3])
        : "r"(a[0]), "r"(a[1]), "r"(a[2]), "r"(a[3]), "r"(b[0]), "r"(b[1]));
}

__device__ __forceinline__ void cp16(void* smem, const void* gmem) {
    uint32_t s = (uint32_t)__cvta_generic_to_shared(smem);
    asm volatile("cp.async.ca.shared.global [%0], [%1], 16;" :: "r"(s), "l"(gmem));
}
#define CP_COMMIT() asm volatile("cp.async.commit_group;" ::)
#define CP_WAIT1()  asm volatile("cp.async.wait_group 1;" ::: "memory")
#define CP_WAIT0()  asm volatile("cp.async.wait_group 0;" ::: "memory")

// ---------------------------------------------------------------------------
// fp32 -> fp16 elementwise (x)
// ---------------------------------------------------------------------------
__global__ __launch_bounds__(256) void cvt_x_kernel(const float* __restrict__ s)
{
    const int i = (blockIdx.x * blockDim.x + threadIdx.x) << 2;
    if (i >= MTOK * EE) return;
    float4 v = *(const float4*)(s + i);
    __half2 h0 = __floats2half2_rn(v.x, v.y);
    __half2 h1 = __floats2half2_rn(v.z, v.w);
    *(__half2*)(g_x + i)     = h0;
    *(__half2*)(g_x + i + 2) = h1;
}

// ---------------------------------------------------------------------------
// fp32 [K][N] -> fp16 [N][K] tiled transpose-convert (weights)
// ---------------------------------------------------------------------------
__device__ __forceinline__ void transpose_body(
    const float* __restrict__ src, half* __restrict__ dst, int K, int N)
{
    __shared__ float tile[32][33];
    const int n = blockIdx.x * 32 + threadIdx.x;
    const int k = blockIdx.y * 32 + threadIdx.y;
    #pragma unroll
    for (int j = 0; j < 32; j += 8)
        tile[threadIdx.y + j][threadIdx.x] = src[(size_t)(k + j) * N + n];
    __syncthreads();
    const int k2 = blockIdx.y * 32 + threadIdx.x;
    const int n2 = blockIdx.x * 32 + threadIdx.y;
    #pragma unroll
    for (int j = 0; j < 32; j += 8)
        dst[(size_t)(n2 + j) * K + k2] =
            __float2half_rn(tile[threadIdx.x][threadIdx.y + j]);
}
__global__ __launch_bounds__(256) void cvt_wa_kernel(const float* __restrict__ s)
{ transpose_body(s, g_wa, EE, E3); }
__global__ __launch_bounds__(256) void cvt_wp_kernel(const float* __restrict__ s)
{ transpose_body(s, g_wp, EE, EE); }

// ---------------------------------------------------------------------------
// RoPE cos/sin table
// ---------------------------------------------------------------------------
__global__ __launch_bounds__(256) void rope_table_kernel(const int* __restrict__ pos)
{
    const int i = blockIdx.x * blockDim.x + threadIdx.x;
    if (i >= BB * LL * 32) return;
    const int bl = i >> 5;
    const int j  = i & 31;
    const float p   = (float)pos[bl];
    const float inv = powf(10000.0f, -(float)j / 32.0f);
    float sn, cs;
    sincosf(p * inv, &sn, &cs);
    g_rope[(size_t)bl * 64 + j]      = cs;
    g_rope[(size_t)bl * 64 + 32 + j] = sn;
}

// ---------------------------------------------------------------------------
// fp16 cp.async double-buffered GEMM (unchanged from passing R11)
// ---------------------------------------------------------------------------
#define KCH 32
#define PH  40

__device__ __forceinline__ void gemm_h(
    const half* __restrict__ A, const half* __restrict__ Wt,
    const float* __restrict__ bias, int K, int mode,
    float* __restrict__ outf)
{
    __shared__ __align__(16) half sA[2][128][PH];   // 20.5 KB
    __shared__ __align__(16) half sB[2][128][PH];   // 20.5 KB

    const int tid   = threadIdx.x;     // 0..127
    const int lane  = tid & 31;
    const int wid   = tid >> 5;        // 0..3
    const int warpM = wid & 1;
    const int warpN = wid >> 1;
    const int lq    = lane >> 2;
    const int lr    = lane & 3;

    const int m0 = blockIdx.y * 128;
    const int n0 = blockIdx.x * 128;
    const int Nn = gridDim.x * 128;

    float acc[4][8][4];
    #pragma unroll
    for (int i = 0; i < 4; i++)
        #pragma unroll
        for (int j = 0; j < 8; j++)
            #pragma unroll
            for (int c = 0; c < 4; c++) acc[i][j][c] = 0.0f;

    const int nch = K / KCH;

    {   // prefetch stage 0
        #pragma unroll
        for (int it = 0; it < 4; it++) {
            const int i   = tid + it * 128;
            const int row = i >> 2;
            const int c8  = (i & 3) << 3;
            cp16(&sA[0][row][c8], A  + (size_t)(m0 + row) * K + c8);
            cp16(&sB[0][row][c8], Wt + (size_t)(n0 + row) * K + c8);
        }
        CP_COMMIT();
    }

    for (int ch = 0; ch < nch; ch++) {
        if (ch + 1 < nch) {
            const int st = (ch + 1) & 1;
            const int k0 = (ch + 1) * KCH;
            #pragma unroll
            for (int it = 0; it < 4; it++) {
                const int i   = tid + it * 128;
                const int row = i >> 2;
                const int c8  = (i & 3) << 3;
                cp16(&sA[st][row][c8], A  + (size_t)(m0 + row) * K + k0 + c8);
                cp16(&sB[st][row][c8], Wt + (size_t)(n0 + row) * K + k0 + c8);
            }
        }
        CP_COMMIT();
        CP_WAIT1();
        __syncthreads();

        const int st = ch & 1;
        #pragma unroll
        for (int s = 0; s < 2; s++) {
            const int s16 = s * 16;
            uint32_t af[4][4], bf[8][2];
            #pragma unroll
            for (int mf = 0; mf < 4; mf++) {
                const int mr = warpM * 64 + mf * 16;
                af[mf][0] = *(const uint32_t*)&sA[st][mr + lq    ][s16 + 2*lr    ];
                af[mf][1] = *(const uint32_t*)&sA[st][mr + lq + 8][s16 + 2*lr    ];
                af[mf][2] = *(const uint32_t*)&sA[st][mr + lq    ][s16 + 2*lr + 8];
                af[mf][3] = *(const uint32_t*)&sA[st][mr + lq + 8][s16 + 2*lr + 8];
            }
            #pragma unroll
            for (int nf = 0; nf < 8; nf++) {
                const int nb = warpN * 64 + nf * 8 + lq;
                bf[nf][0] = *(const uint32_t*)&sB[st][nb][s16 + 2*lr    ];
                bf[nf][1] = *(const uint32_t*)&sB[st][nb][s16 + 2*lr + 8];
            }
            #pragma unroll
            for (int mf = 0; mf < 4; mf++)
                #pragma unroll
                for (int nf = 0; nf < 8; nf++)
                    mma_f16(acc[mf][nf], af[mf], bf[nf]);
        }
        __syncthreads();
    }

    // ---- epilogue ----
    const int gc0 = n0 + warpN * 64;
    const int q2  = lr * 2;

    float b0[8], b1[8];
    #pragma unroll
    for (int nf = 0; nf < 8; nf++) {
        b0[nf] = bias[gc0 + nf * 8 + q2];
        b1[nf] = bias[gc0 + nf * 8 + q2 + 1];
    }

    #pragma unroll
    for (int mf = 0; mf < 4; mf++) {
        #pragma unroll
        for (int rs = 0; rs < 2; rs++) {
            const int row = warpM * 64 + mf * 16 + lq + rs * 8;
            const int t   = m0 + row;
            float v[8][2];
            #pragma unroll
            for (int nf = 0; nf < 8; nf++) {
                v[nf][0] = acc[mf][nf][rs * 2]     + b0[nf];
                v[nf][1] = acc[mf][nf][rs * 2 + 1] + b1[nf];
            }
            if (mode == 0) {
                float* Crow = outf + (size_t)t * Nn + gc0;
                #pragma unroll
                for (int nf = 0; nf < 8; nf++)
                    *(float2*)(Crow + nf * 8 + q2) = make_float2(v[nf][0], v[nf][1]);
            } else if (gc0 < 1024) {
                const float* rt = g_rope +
                    (size_t)((t >> 13) * LL + ((t >> 3) & (LL - 1))) * 64;
                #pragma unroll
                for (int nf = 0; nf < 4; nf++) {
                    const int j = nf * 8 + q2;
                    const float cs0 = rt[j],     sn0 = rt[32 + j];
                    const float cs1 = rt[j + 1], sn1 = rt[33 + j];
                    const float x0 = v[nf][0], y0 = v[nf + 4][0];
                    const float x1 = v[nf][1], y1 = v[nf + 4][1];
                    v[nf][0]     = x0 * cs0 - y0 * sn0;
                    v[nf + 4][0] = y0 * cs0 + x0 * sn0;
                    v[nf][1]     = x1 * cs1 - y1 * sn1;
                    v[nf + 4][1] = y1 * cs1 + x1 * sn1;
                }
                half* Crow = g_qkv + (size_t)t * 1024 + gc0;
                #pragma unroll
                for (int nf = 0; nf < 8; nf++)
                    *(__half2*)(Crow + nf * 8 + q2) =
                        __floats2half2_rn(v[nf][0], v[nf][1]);
            } else {
                const int bb_ = t >> 13;
                const int nn_ = t & 7;
                const int ll_ = (t >> 3) & (LL - 1);
                #pragma unroll
                for (int nf = 0; nf < 8; nf++) {
                    const int dg = gc0 + nf * 8 + q2 - 1024;
                    const int h_ = dg >> 6;
                    const int d_ = dg & 63;
                    const size_t base =
                        (((size_t)((bb_ * NN + nn_) * HH + h_) * HD) + d_) * LL + ll_;
                    g_v[base]      = __float2half_rn(v[nf][0]);
                    g_v[base + LL] = __float2half_rn(v[nf][1]);
                }
            }
        }
    }
}

__global__ __launch_bounds__(128) void qkv_mma_kernel(const float* __restrict__ b_attn)
{
    gemm_h(g_x, g_wa, b_attn, EE, 1, (float*)0);
}

__global__ __launch_bounds__(128) void proj_mma_kernel(
    const float* __restrict__ b_proj, float* __restrict__ out)
{
    gemm_h(g_y, g_wp, b_proj, EE, 0, out);
}

// ---------------------------------------------------------------------------
// Flash attention, fp16 m16n8k16, BQ=128 (8 warps, 256 thr), smem P.
// sQP 128x72 (Q staging, then P), sK 64x72, sVt 64x72 -> 36.8 KB static.
// One block barrier per kv tile; P rows warp-private (syncwarp only).
// ---------------------------------------------------------------------------
#define ABQ 128
#define AKV 64
#define PAH 72

__global__ __launch_bounds__(256) void attn_mma_kernel()
{
    __shared__ __align__(16) half sQP[ABQ][PAH];  // Q staging, then P
    __shared__ __align__(16) half sK [AKV][PAH];  // K  [kv][hd]
    __shared__ __align__(16) half sVt[HD][PAH];   // V^T [d][kv]

    const int bnh  = blockIdx.y;
    const int h    = bnh & 7;
    const int n    = (bnh >> 3) & 7;
    const int b    = bnh >> 6;
    const int qt   = blockIdx.x;          // 0..7, 128 q rows each

    const int tid  = threadIdx.x;
    const int lane = tid & 31;
    const int wid  = tid >> 5;            // 0..7
    const int lq   = lane >> 2;
    const int lr   = lane & 3;
    const int w16  = wid * 16;

    const size_t vbase = (size_t)bnh * HD * LL;

    // ---- stage Q (128 x 64 halves) via cp.async ----
    #pragma unroll
    for (int it = 0; it < 4; it++) {
        const int i  = tid + it * 256;      // 0..1023
        const int r  = i >> 3;
        const int c8 = (i & 7) << 3;
        cp16(&sQP[r][c8],
             g_qkv + (size_t)((b * LL + qt * ABQ + r) * NN + n) * 1024 + h * HD + c8);
    }
    CP_COMMIT();
    CP_WAIT0();
    __syncthreads();

    // ---- preload Q fragments (16 rows per warp) ----
    uint32_t aq[4][4];
    #pragma unroll
    for (int ks = 0; ks < 4; ks++) {
        const int k0 = ks * 16;
        aq[ks][0] = *(const uint32_t*)&sQP[w16 + lq    ][k0 + 2*lr    ];
        aq[ks][1] = *(const uint32_t*)&sQP[w16 + lq + 8][k0 + 2*lr    ];
        aq[ks][2] = *(const uint32_t*)&sQP[w16 + lq    ][k0 + 2*lr + 8];
        aq[ks][3] = *(const uint32_t*)&sQP[w16 + lq + 8][k0 + 2*lr + 8];
    }

    float m_run[2] = {-1e30f, -1e30f};
    float l_run[2] = {0.0f, 0.0f};
    float acc[8][4];
    #pragma unroll
    for (int nf = 0; nf < 8; nf++)
        #pragma unroll
        for (int c = 0; c < 4; c++) acc[nf][c] = 0.0f;

    const int gr0 = qt * ABQ + w16 + lq;  // global q row of c0/c1
    const int gr1 = gr0 + 8;

    const int nT = 2 * (qt + 1);          // kv tiles of 64
    for (int kt = 0; kt < nT; kt++) {
        __syncthreads();   // prior tile done with sK/sVt (and P in sQP)

        // ---- stage K [kv][hd] and V^T [d][kv] via cp.async ----
        #pragma unroll
        for (int it = 0; it < 2; it++) {
            const int i  = tid + it * 256;  // 0..511
            const int r  = i >> 3;
            const int c8 = (i & 7) << 3;
            cp16(&sK[r][c8],
                 g_qkv + (size_t)((b * LL + kt * AKV + r) * NN + n) * 1024
                       + 512 + h * HD + c8);
            cp16(&sVt[r][c8], g_v + vbase + (size_t)r * LL + kt * AKV + c8);
        }
        CP_COMMIT();
        CP_WAIT0();
        __syncthreads();

        // ---- S = Q K^T (32 mma/warp) ----
        float s[8][4];
        #pragma unroll
        for (int nf = 0; nf < 8; nf++)
            #pragma unroll
            for (int c = 0; c < 4; c++) s[nf][c] = 0.0f;

        #pragma unroll
        for (int ks = 0; ks < 4; ks++) {
            const int k0 = ks * 16;
            #pragma unroll
            for (int nf = 0; nf < 8; nf++) {
                uint32_t bb[2];
                bb[0] = *(const uint32_t*)&sK[nf * 8 + lq][k0 + 2*lr    ];
                bb[1] = *(const uint32_t*)&sK[nf * 8 + lq][k0 + 2*lr + 8];
                mma_f16(s[nf], aq[ks], bb);
            }
        }

        // ---- scale + causal mask + online softmax ----
        const bool needmask = (kt >= 2 * qt);
        const int  r0l = w16 + lq;
        const int  r1l = r0l + 8;
        float mx0 = -1e30f, mx1 = -1e30f;
        #pragma unroll
        for (int nf = 0; nf < 8; nf++) {
            #pragma unroll
            for (int c = 0; c < 2; c++) {
                const int gcol = kt * AKV + nf * 8 + 2 * lr + c;
                float v0 = s[nf][c]     * 0.125f;
                float v1 = s[nf][2 + c] * 0.125f;
                if (needmask && gcol > gr0) v0 = -1e30f;
                if (needmask && gcol > gr1) v1 = -1e30f;
                s[nf][c]     = v0;
                s[nf][2 + c] = v1;
                mx0 = fmaxf(mx0, v0);
                mx1 = fmaxf(mx1, v1);
            }
        }
        #pragma unroll
        for (int off = 1; off < 4; off <<= 1) {
            mx0 = fmaxf(mx0, __shfl_xor_sync(0xffffffffu, mx0, off));
            mx1 = fmaxf(mx1, __shfl_xor_sync(0xffffffffu, mx1, off));
        }

        const float mn0 = fmaxf(m_run[0], mx0);
        const float mn1 = fmaxf(m_run[1], mx1);
        const float al0 = __expf(m_run[0] - mn0);
        const float al1 = __expf(m_run[1] - mn1);
        m_run[0] = mn0; m_run[1] = mn1;

        float sum0 = 0.0f, sum1 = 0.0f;
        #pragma unroll
        for (int nf = 0; nf < 8; nf++) {
            const float p00 = __expf(s[nf][0] - mn0);
            const float p01 = __expf(s[nf][1] - mn0);
            const float p10 = __expf(s[nf][2] - mn1);
            const float p11 = __expf(s[nf][3] - mn1);
            sum0 += p00 + p01;
            sum1 += p10 + p11;
            const int cc = nf * 8 + 2 * lr;
            *(__half2*)&sQP[r0l][cc] = __floats2half2_rn(p00, p01);
            *(__half2*)&sQP[r1l][cc] = __floats2half2_rn(p10, p11);
        }
        #pragma unroll
        for (int off = 1; off < 4; off <<= 1) {
            sum0 += __shfl_xor_sync(0xffffffffu, sum0, off);
            sum1 += __shfl_xor_sync(0xffffffffu, sum1, off);
        }
        l_run[0] = l_run[0] * al0 + sum0;
        l_run[1] = l_run[1] * al1 + sum1;

        #pragma unroll
        for (int nf = 0; nf < 8; nf++) {
            acc[nf][0] *= al0; acc[nf][1] *= al0;
            acc[nf][2] *= al1; acc[nf][3] *= al1;
        }
        __syncwarp();      // P rows warp-private

        // ---- O += P V (32 mma/warp) ----
        #pragma unroll
        for (int ks = 0; ks < 4; ks++) {
            const int k0 = ks * 16;
            uint32_t ap[4];
            ap[0] = *(const uint32_t*)&sQP[r0l][k0 + 2*lr    ];
            ap[1] = *(const uint32_t*)&sQP[r1l][k0 + 2*lr    ];
            ap[2] = *(const uint32_t*)&sQP[r0l][k0 + 2*lr + 8];
            ap[3] = *(const uint32_t*)&sQP[r1l][k0 + 2*lr + 8];
            #pragma unroll
            for (int nf = 0; nf < 8; nf++) {
                uint32_t bb[2];
                bb[0] = *(const uint32_t*)&sVt[nf * 8 + lq][k0 + 2*lr    ];
                bb[1] = *(const uint32_t*)&sVt[nf * 8 + lq][k0 + 2*lr + 8];
                mma_f16(acc[nf], ap, bb);
            }
        }
    }

    // ---- epilogue: normalize + half store to g_y ----
    const float inv0 = 1.0f / l_run[0];
    const float inv1 = 1.0f / l_run[1];
    half* y0 = g_y + (size_t)((b * LL + gr0) * NN + n) * EE + h * HD;
    half* y1 = g_y + (size_t)((b * LL + gr1) * NN + n) * EE + h * HD;
    #pragma unroll
    for (int nf = 0; nf < 8; nf++) {
        const int cc = nf * 8 + 2 * lr;
        *(__half2*)(y0 + cc) = __floats2half2_rn(acc[nf][0] * inv0,
                                                 acc[nf][1] * inv0);
        *(__half2*)(y1 + cc) = __floats2half2_rn(acc[nf][2] * inv1,
                                                 acc[nf][3] * inv1);
    }
}

// ---------------------------------------------------------------------------
// launch
// ---------------------------------------------------------------------------
extern "C" void kernel_launch(void* const* d_in, const int* in_sizes, int n_in,
                              void* d_out, int out_size)
{
    const float* x      = (const float*)d_in[0];
    const int*   pos    = (const int*)  d_in[1];
    const float* w_attn = (const float*)d_in[2];
    const float* b_attn = (const float*)d_in[3];
    const float* w_proj = (const float*)d_in[4];
    const float* b_proj = (const float*)d_in[5];
    float*       out    = (float*)d_out;

    // 0) convert x -> fp16; transpose-convert weights -> [n][k] fp16
    cvt_x_kernel<<<(MTOK * EE / 4 + 255) / 256, 256>>>(x);
    cvt_wa_kernel<<<dim3(E3 / 32, EE / 32), dim3(32, 8)>>>(w_attn);
    cvt_wp_kernel<<<dim3(EE / 32, EE / 32), dim3(32, 8)>>>(w_proj);

    // 1) cos/sin table
    rope_table_kernel<<<(BB * LL * 32) / 256, 256>>>(pos);

    // 2) QKV fp16 GEMM + fused bias + RoPE; V stored transposed
    qkv_mma_kernel<<<dim3(E3 / 128, MTOK / 128), 128>>>(b_attn);

    // 3) causal flash attention (fp16, BQ=128) -> g_y
    attn_mma_kernel<<<dim3(LL / ABQ, BB * NN * HH), 256>>>();

    // 4) out = y @ w_proj + b_proj (fp32 store)
    proj_mma_kernel<<<dim3(EE / 128, MTOK / 128), 128>>>(b_proj, out);
}

// round 13
// speedup vs baseline: 1.0376x; 1.0376x over previous
#include <cuda_runtime.h>
#include <cuda_fp16.h>
#include <math.h>
#include <stdint.h>

// Problem dims (fixed by the dataset)
#define BB    2
#define LL    1024
#define NN    8
#define EE    512
#define HH    8
#define HD    64
#define E3    1536
#define MTOK  (BB * LL * NN)          // 16384 tokens

// ---------------------------------------------------------------------------
// Scratch (device globals)
// ---------------------------------------------------------------------------
__device__ half  g_qkv [(size_t)MTOK * 1024];        // [token][1024] q|k post-RoPE
__device__ half  g_v   [(size_t)BB * NN * HH * HD * LL]; // [bnh][d][L] V transposed
__device__ half  g_y   [(size_t)MTOK * EE];          // attention out
__device__ float g_rope[(size_t)BB * LL * 64];       // [b*L+l][cos32|sin32]
__device__ half  g_x   [(size_t)MTOK * EE];          // x fp16
__device__ half  g_wa  [(size_t)E3 * EE];            // w_attn^T  [n][k] fp16
__device__ half  g_wp  [(size_t)EE * EE];            // w_proj^T  [n][k] fp16

// ---------------------------------------------------------------------------
// helpers
// ---------------------------------------------------------------------------
__device__ __forceinline__ void mma_f16(float* c, const uint32_t* a,
                                        const uint32_t* b) {
    asm volatile(
        "mma.sync.aligned.m16n8k16.row.col.f32.f16.f16.f32 "
        "{%0,%1,%2,%3}, {%4,%5,%6,%7}, {%8,%9}, {%0,%1,%2,%3};"
        : "+f"(c[0]), "+f"(c[1]), "+f"(c[2]), "+f"(c[3])
        : "r"(a[0]), "r"(a[1]), "r"(a[2]), "r"(a[3]), "r"(b[0]), "r"(b[1]));
}

__device__ __forceinline__ void cp16(void* smem, const void* gmem) {
    uint32_t s = (uint32_t)__cvta_generic_to_shared(smem);
    asm volatile("cp.async.ca.shared.global [%0], [%1], 16;" :: "r"(s), "l"(gmem));
}
#define CP_COMMIT() asm volatile("cp.async.commit_group;" ::)
#define CP_WAIT1()  asm volatile("cp.async.wait_group 1;" ::: "memory")
#define CP_WAIT0()  asm volatile("cp.async.wait_group 0;" ::: "memory")

// ---------------------------------------------------------------------------
// fp32 -> fp16 elementwise (x)
// ---------------------------------------------------------------------------
__global__ __launch_bounds__(256) void cvt_x_kernel(const float* __restrict__ s)
{
    const int i = (blockIdx.x * blockDim.x + threadIdx.x) << 2;
    if (i >= MTOK * EE) return;
    float4 v = *(const float4*)(s + i);
    __half2 h0 = __floats2half2_rn(v.x, v.y);
    __half2 h1 = __floats2half2_rn(v.z, v.w);
    *(__half2*)(g_x + i)     = h0;
    *(__half2*)(g_x + i + 2) = h1;
}

// ---------------------------------------------------------------------------
// fp32 [K][N] -> fp16 [N][K] tiled transpose-convert (weights)
// ---------------------------------------------------------------------------
__device__ __forceinline__ void transpose_body(
    const float* __restrict__ src, half* __restrict__ dst, int K, int N)
{
    __shared__ float tile[32][33];
    const int n = blockIdx.x * 32 + threadIdx.x;
    const int k = blockIdx.y * 32 + threadIdx.y;
    #pragma unroll
    for (int j = 0; j < 32; j += 8)
        tile[threadIdx.y + j][threadIdx.x] = src[(size_t)(k + j) * N + n];
    __syncthreads();
    const int k2 = blockIdx.y * 32 + threadIdx.x;
    const int n2 = blockIdx.x * 32 + threadIdx.y;
    #pragma unroll
    for (int j = 0; j < 32; j += 8)
        dst[(size_t)(n2 + j) * K + k2] =
            __float2half_rn(tile[threadIdx.x][threadIdx.y + j]);
}
__global__ __launch_bounds__(256) void cvt_wa_kernel(const float* __restrict__ s)
{ transpose_body(s, g_wa, EE, E3); }
__global__ __launch_bounds__(256) void cvt_wp_kernel(const float* __restrict__ s)
{ transpose_body(s, g_wp, EE, EE); }

// ---------------------------------------------------------------------------
// RoPE cos/sin table
// ---------------------------------------------------------------------------
__global__ __launch_bounds__(256) void rope_table_kernel(const int* __restrict__ pos)
{
    const int i = blockIdx.x * blockDim.x + threadIdx.x;
    if (i >= BB * LL * 32) return;
    const int bl = i >> 5;
    const int j  = i & 31;
    const float p   = (float)pos[bl];
    const float inv = powf(10000.0f, -(float)j / 32.0f);
    float sn, cs;
    sincosf(p * inv, &sn, &cs);
    g_rope[(size_t)bl * 64 + j]      = cs;
    g_rope[(size_t)bl * 64 + 32 + j] = sn;
}

// ---------------------------------------------------------------------------
// fp16 cp.async double-buffered GEMM (unchanged from passing R11)
// ---------------------------------------------------------------------------
#define KCH 32
#define PH  40

__device__ __forceinline__ void gemm_h(
    const half* __restrict__ A, const half* __restrict__ Wt,
    const float* __restrict__ bias, int K, int mode,
    float* __restrict__ outf)
{
    __shared__ __align__(16) half sA[2][128][PH];   // 20.5 KB
    __shared__ __align__(16) half sB[2][128][PH];   // 20.5 KB

    const int tid   = threadIdx.x;     // 0..127
    const int lane  = tid & 31;
    const int wid   = tid >> 5;        // 0..3
    const int warpM = wid & 1;
    const int warpN = wid >> 1;
    const int lq    = lane >> 2;
    const int lr    = lane & 3;

    const int m0 = blockIdx.y * 128;
    const int n0 = blockIdx.x * 128;
    const int Nn = gridDim.x * 128;

    float acc[4][8][4];
    #pragma unroll
    for (int i = 0; i < 4; i++)
        #pragma unroll
        for (int j = 0; j < 8; j++)
            #pragma unroll
            for (int c = 0; c < 4; c++) acc[i][j][c] = 0.0f;

    const int nch = K / KCH;

    {   // prefetch stage 0
        #pragma unroll
        for (int it = 0; it < 4; it++) {
            const int i   = tid + it * 128;
            const int row = i >> 2;
            const int c8  = (i & 3) << 3;
            cp16(&sA[0][row][c8], A  + (size_t)(m0 + row) * K + c8);
            cp16(&sB[0][row][c8], Wt + (size_t)(n0 + row) * K + c8);
        }
        CP_COMMIT();
    }

    for (int ch = 0; ch < nch; ch++) {
        if (ch + 1 < nch) {
            const int st = (ch + 1) & 1;
            const int k0 = (ch + 1) * KCH;
            #pragma unroll
            for (int it = 0; it < 4; it++) {
                const int i   = tid + it * 128;
                const int row = i >> 2;
                const int c8  = (i & 3) << 3;
                cp16(&sA[st][row][c8], A  + (size_t)(m0 + row) * K + k0 + c8);
                cp16(&sB[st][row][c8], Wt + (size_t)(n0 + row) * K + k0 + c8);
            }
        }
        CP_COMMIT();
        CP_WAIT1();
        __syncthreads();

        const int st = ch & 1;
        #pragma unroll
        for (int s = 0; s < 2; s++) {
            const int s16 = s * 16;
            uint32_t af[4][4], bf[8][2];
            #pragma unroll
            for (int mf = 0; mf < 4; mf++) {
                const int mr = warpM * 64 + mf * 16;
                af[mf][0] = *(const uint32_t*)&sA[st][mr + lq    ][s16 + 2*lr    ];
                af[mf][1] = *(const uint32_t*)&sA[st][mr + lq + 8][s16 + 2*lr    ];
                af[mf][2] = *(const uint32_t*)&sA[st][mr + lq    ][s16 + 2*lr + 8];
                af[mf][3] = *(const uint32_t*)&sA[st][mr + lq + 8][s16 + 2*lr + 8];
            }
            #pragma unroll
            for (int nf = 0; nf < 8; nf++) {
                const int nb = warpN * 64 + nf * 8 + lq;
                bf[nf][0] = *(const uint32_t*)&sB[st][nb][s16 + 2*lr    ];
                bf[nf][1] = *(const uint32_t*)&sB[st][nb][s16 + 2*lr + 8];
            }
            #pragma unroll
            for (int mf = 0; mf < 4; mf++)
                #pragma unroll
                for (int nf = 0; nf < 8; nf++)
                    mma_f16(acc[mf][nf], af[mf], bf[nf]);
        }
        __syncthreads();
    }

    // ---- epilogue ----
    const int gc0 = n0 + warpN * 64;
    const int q2  = lr * 2;

    float b0[8], b1[8];
    #pragma unroll
    for (int nf = 0; nf < 8; nf++) {
        b0[nf] = bias[gc0 + nf * 8 + q2];
        b1[nf] = bias[gc0 + nf * 8 + q2 + 1];
    }

    #pragma unroll
    for (int mf = 0; mf < 4; mf++) {
        #pragma unroll
        for (int rs = 0; rs < 2; rs++) {
            const int row = warpM * 64 + mf * 16 + lq + rs * 8;
            const int t   = m0 + row;
            float v[8][2];
            #pragma unroll
            for (int nf = 0; nf < 8; nf++) {
                v[nf][0] = acc[mf][nf][rs * 2]     + b0[nf];
                v[nf][1] = acc[mf][nf][rs * 2 + 1] + b1[nf];
            }
            if (mode == 0) {
                float* Crow = outf + (size_t)t * Nn + gc0;
                #pragma unroll
                for (int nf = 0; nf < 8; nf++)
                    *(float2*)(Crow + nf * 8 + q2) = make_float2(v[nf][0], v[nf][1]);
            } else if (gc0 < 1024) {
                const float* rt = g_rope +
                    (size_t)((t >> 13) * LL + ((t >> 3) & (LL - 1))) * 64;
                #pragma unroll
                for (int nf = 0; nf < 4; nf++) {
                    const int j = nf * 8 + q2;
                    const float cs0 = rt[j],     sn0 = rt[32 + j];
                    const float cs1 = rt[j + 1], sn1 = rt[33 + j];
                    const float x0 = v[nf][0], y0 = v[nf + 4][0];
                    const float x1 = v[nf][1], y1 = v[nf + 4][1];
                    v[nf][0]     = x0 * cs0 - y0 * sn0;
                    v[nf + 4][0] = y0 * cs0 + x0 * sn0;
                    v[nf][1]     = x1 * cs1 - y1 * sn1;
                    v[nf + 4][1] = y1 * cs1 + x1 * sn1;
                }
                half* Crow = g_qkv + (size_t)t * 1024 + gc0;
                #pragma unroll
                for (int nf = 0; nf < 8; nf++)
                    *(__half2*)(Crow + nf * 8 + q2) =
                        __floats2half2_rn(v[nf][0], v[nf][1]);
            } else {
                const int bb_ = t >> 13;
                const int nn_ = t & 7;
                const int ll_ = (t >> 3) & (LL - 1);
                #pragma unroll
                for (int nf = 0; nf < 8; nf++) {
                    const int dg = gc0 + nf * 8 + q2 - 1024;
                    const int h_ = dg >> 6;
                    const int d_ = dg & 63;
                    const size_t base =
                        (((size_t)((bb_ * NN + nn_) * HH + h_) * HD) + d_) * LL + ll_;
                    g_v[base]      = __float2half_rn(v[nf][0]);
                    g_v[base + LL] = __float2half_rn(v[nf][1]);
                }
            }
        }
    }
}

__global__ __launch_bounds__(128) void qkv_mma_kernel(const float* __restrict__ b_attn)
{
    gemm_h(g_x, g_wa, b_attn, EE, 1, (float*)0);
}

__global__ __launch_bounds__(128) void proj_mma_kernel(
    const float* __restrict__ b_proj, float* __restrict__ out)
{
    gemm_h(g_y, g_wp, b_proj, EE, 0, out);
}

// ---------------------------------------------------------------------------
// Flash attention, fp16 m16n8k16, BQ=64 (4 warps), DOUBLE-BUFFERED K/V.
// sQP 64x72 (Q staging, then P) + sK[2] + sVt[2] (64x72 each) = 46.1 KB.
// Tile kt+1 prefetch overlaps tile kt compute via cp.async wait_group 1.
// ---------------------------------------------------------------------------
#define AKV 64
#define PAH 72

__global__ __launch_bounds__(128) void attn_mma_kernel()
{
    __shared__ __align__(16) half sQP[64][PAH];      // Q staging, then P
    __shared__ __align__(16) half sK [2][AKV][PAH];  // K  [kv][hd], 2 stages
    __shared__ __align__(16) half sVt[2][HD][PAH];   // V^T [d][kv], 2 stages

    const int bnh  = blockIdx.y;
    const int h    = bnh & 7;
    const int n    = (bnh >> 3) & 7;
    const int b    = bnh >> 6;
    const int qt   = blockIdx.x;

    const int tid  = threadIdx.x;
    const int lane = tid & 31;
    const int wid  = tid >> 5;
    const int lq   = lane >> 2;
    const int lr   = lane & 3;
    const int w16  = wid * 16;

    const size_t vbase = (size_t)bnh * HD * LL;

    // ---- stage Q (group 0) ----
    #pragma unroll
    for (int it = 0; it < 4; it++) {
        const int i  = tid + it * 128;      // 0..511
        const int r  = i >> 3;
        const int c8 = (i & 7) << 3;
        cp16(&sQP[r][c8],
             g_qkv + (size_t)((b * LL + qt * 64 + r) * NN + n) * 1024 + h * HD + c8);
    }
    CP_COMMIT();

    // ---- prefetch kv tile 0 into stage 0 (group 1) ----
    #pragma unroll
    for (int it = 0; it < 4; it++) {
        const int i  = tid + it * 128;
        const int r  = i >> 3;
        const int c8 = (i & 7) << 3;
        cp16(&sK[0][r][c8],
             g_qkv + (size_t)((b * LL + r) * NN + n) * 1024 + 512 + h * HD + c8);
        cp16(&sVt[0][r][c8], g_v + vbase + (size_t)r * LL + c8);
    }
    CP_COMMIT();

    CP_WAIT1();        // Q resident (kv0 may still be in flight)
    __syncthreads();

    // ---- preload Q fragments ----
    uint32_t aq[4][4];
    #pragma unroll
    for (int ks = 0; ks < 4; ks++) {
        const int k0 = ks * 16;
        aq[ks][0] = *(const uint32_t*)&sQP[w16 + lq    ][k0 + 2*lr    ];
        aq[ks][1] = *(const uint32_t*)&sQP[w16 + lq + 8][k0 + 2*lr    ];
        aq[ks][2] = *(const uint32_t*)&sQP[w16 + lq    ][k0 + 2*lr + 8];
        aq[ks][3] = *(const uint32_t*)&sQP[w16 + lq + 8][k0 + 2*lr + 8];
    }

    float m_run[2] = {-1e30f, -1e30f};
    float l_run[2] = {0.0f, 0.0f};
    float acc[8][4];
    #pragma unroll
    for (int nf = 0; nf < 8; nf++)
        #pragma unroll
        for (int c = 0; c < 4; c++) acc[nf][c] = 0.0f;

    const int nT = qt + 1;
    for (int kt = 0; kt < nT; kt++) {
        // ---- prefetch tile kt+1 into stage (kt+1)&1 ----
        if (kt + 1 < nT) {
            const int st = (kt + 1) & 1;
            #pragma unroll
            for (int it = 0; it < 4; it++) {
                const int i  = tid + it * 128;
                const int r  = i >> 3;
                const int c8 = (i & 7) << 3;
                cp16(&sK[st][r][c8],
                     g_qkv + (size_t)((b * LL + (kt + 1) * AKV + r) * NN + n) * 1024
                           + 512 + h * HD + c8);
                cp16(&sVt[st][r][c8],
                     g_v + vbase + (size_t)r * LL + (kt + 1) * AKV + c8);
            }
        }
        CP_COMMIT();
        CP_WAIT1();        // tile kt resident; kt+1 in flight
        __syncthreads();

        const int st = kt & 1;

        // ---- S = Q K^T  (32 mma) ----
        float s[8][4];
        #pragma unroll
        for (int nf = 0; nf < 8; nf++)
            #pragma unroll
            for (int c = 0; c < 4; c++) s[nf][c] = 0.0f;

        #pragma unroll
        for (int ks = 0; ks < 4; ks++) {
            const int k0 = ks * 16;
            #pragma unroll
            for (int nf = 0; nf < 8; nf++) {
                uint32_t bb[2];
                bb[0] = *(const uint32_t*)&sK[st][nf * 8 + lq][k0 + 2*lr    ];
                bb[1] = *(const uint32_t*)&sK[st][nf * 8 + lq][k0 + 2*lr + 8];
                mma_f16(s[nf], aq[ks], bb);
            }
        }

        // ---- scale + causal mask + online softmax ----
        const bool diag = (kt == qt);
        const int  r0l  = w16 + lq;
        const int  r1l  = r0l + 8;
        float mx0 = -1e30f, mx1 = -1e30f;
        #pragma unroll
        for (int nf = 0; nf < 8; nf++) {
            #pragma unroll
            for (int c = 0; c < 2; c++) {
                const int col = nf * 8 + 2 * lr + c;
                float v0 = s[nf][c]     * 0.125f;
                float v1 = s[nf][2 + c] * 0.125f;
                if (diag && col > r0l) v0 = -1e30f;
                if (diag && col > r1l) v1 = -1e30f;
                s[nf][c]     = v0;
                s[nf][2 + c] = v1;
                mx0 = fmaxf(mx0, v0);
                mx1 = fmaxf(mx1, v1);
            }
        }
        #pragma unroll
        for (int off = 1; off < 4; off <<= 1) {
            mx0 = fmaxf(mx0, __shfl_xor_sync(0xffffffffu, mx0, off));
            mx1 = fmaxf(mx1, __shfl_xor_sync(0xffffffffu, mx1, off));
        }

        const float mn0 = fmaxf(m_run[0], mx0);
        const float mn1 = fmaxf(m_run[1], mx1);
        const float al0 = __expf(m_run[0] - mn0);
        const float al1 = __expf(m_run[1] - mn1);
        m_run[0] = mn0; m_run[1] = mn1;

        float sum0 = 0.0f, sum1 = 0.0f;
        #pragma unroll
        for (int nf = 0; nf < 8; nf++) {
            const float p00 = __expf(s[nf][0] - mn0);
            const float p01 = __expf(s[nf][1] - mn0);
            const float p10 = __expf(s[nf][2] - mn1);
            const float p11 = __expf(s[nf][3] - mn1);
            sum0 += p00 + p01;
            sum1 += p10 + p11;
            const int cc = nf * 8 + 2 * lr;
            *(__half2*)&sQP[r0l][cc] = __floats2half2_rn(p00, p01);
            *(__half2*)&sQP[r1l][cc] = __floats2half2_rn(p10, p11);
        }
        #pragma unroll
        for (int off = 1; off < 4; off <<= 1) {
            sum0 += __shfl_xor_sync(0xffffffffu, sum0, off);
            sum1 += __shfl_xor_sync(0xffffffffu, sum1, off);
        }
        l_run[0] = l_run[0] * al0 + sum0;
        l_run[1] = l_run[1] * al1 + sum1;

        #pragma unroll
        for (int nf = 0; nf < 8; nf++) {
            acc[nf][0] *= al0; acc[nf][1] *= al0;
            acc[nf][2] *= al1; acc[nf][3] *= al1;
        }
        __syncwarp();      // P rows warp-private

        // ---- O += P V  (32 mma) ----
        #pragma unroll
        for (int ks = 0; ks < 4; ks++) {
            const int k0 = ks * 16;
            uint32_t ap[4];
            ap[0] = *(const uint32_t*)&sQP[r0l][k0 + 2*lr    ];
            ap[1] = *(const uint32_t*)&sQP[r1l][k0 + 2*lr    ];
            ap[2] = *(const uint32_t*)&sQP[r0l][k0 + 2*lr + 8];
            ap[3] = *(const uint32_t*)&sQP[r1l][k0 + 2*lr + 8];
            #pragma unroll
            for (int nf = 0; nf < 8; nf++) {
                uint32_t bb[2];
                bb[0] = *(const uint32_t*)&sVt[st][nf * 8 + lq][k0 + 2*lr    ];
                bb[1] = *(const uint32_t*)&sVt[st][nf * 8 + lq][k0 + 2*lr + 8];
                mma_f16(acc[nf], ap, bb);
            }
        }
        __syncthreads();   // stage st free for the prefetch in iteration kt+1
    }

    // ---- epilogue: normalize + half store to g_y ----
    const float inv0 = 1.0f / l_run[0];
    const float inv1 = 1.0f / l_run[1];
    const int gr0 = qt * 64 + w16 + lq;
    const int gr1 = gr0 + 8;
    half* y0 = g_y + (size_t)((b * LL + gr0) * NN + n) * EE + h * HD;
    half* y1 = g_y + (size_t)((b * LL + gr1) * NN + n) * EE + h * HD;
    #pragma unroll
    for (int nf = 0; nf < 8; nf++) {
        const int cc = nf * 8 + 2 * lr;
        *(__half2*)(y0 + cc) = __floats2half2_rn(acc[nf][0] * inv0,
                                                 acc[nf][1] * inv0);
        *(__half2*)(y1 + cc) = __floats2half2_rn(acc[nf][2] * inv1,
                                                 acc[nf][3] * inv1);
    }
}

// ---------------------------------------------------------------------------
// launch
// ---------------------------------------------------------------------------
extern "C" void kernel_launch(void* const* d_in, const int* in_sizes, int n_in,
                              void* d_out, int out_size)
{
    const float* x      = (const float*)d_in[0];
    const int*   pos    = (const int*)  d_in[1];
    const float* w_attn = (const float*)d_in[2];
    const float* b_attn = (const float*)d_in[3];
    const float* w_proj = (const float*)d_in[4];
    const float* b_proj = (const float*)d_in[5];
    float*       out    = (float*)d_out;

    // 0) convert x -> fp16; transpose-convert weights -> [n][k] fp16
    cvt_x_kernel<<<(MTOK * EE / 4 + 255) / 256, 256>>>(x);
    cvt_wa_kernel<<<dim3(E3 / 32, EE / 32), dim3(32, 8)>>>(w_attn);
    cvt_wp_kernel<<<dim3(EE / 32, EE / 32), dim3(32, 8)>>>(w_proj);

    // 1) cos/sin table
    rope_table_kernel<<<(BB * LL * 32) / 256, 256>>>(pos);

    // 2) QKV fp16 GEMM + fused bias + RoPE; V stored transposed
    qkv_mma_kernel<<<dim3(E3 / 128, MTOK / 128), 128>>>(b_attn);

    // 3) causal flash attention (fp16, BQ=64, double-buffered K/V) -> g_y
    attn_mma_kernel<<<dim3(LL / 64, BB * NN * HH), 128>>>();

    // 4) out = y @ w_proj + b_proj (fp32 store)
    proj_mma_kernel<<<dim3(EE / 128, MTOK / 128), 128>>>(b_proj, out);
}

// round 14
// speedup vs baseline: 1.0442x; 1.0064x over previous
#include <cuda_runtime.h>
#include <cuda_fp16.h>
#include <math.h>
#include <stdint.h>

// Problem dims (fixed by the dataset)
#define BB    2
#define LL    1024
#define NN    8
#define EE    512
#define HH    8
#define HD    64
#define E3    1536
#define MTOK  (BB * LL * NN)          // 16384 tokens

// ---------------------------------------------------------------------------
// Scratch (device globals)
// ---------------------------------------------------------------------------
__device__ half  g_qkv [(size_t)MTOK * 1024];        // [token][1024] q|k post-RoPE
__device__ half  g_v   [(size_t)BB * NN * HH * HD * LL]; // [bnh][d][L] V transposed
__device__ half  g_y   [(size_t)MTOK * EE];          // attention out
__device__ float g_rope[(size_t)BB * LL * 64];       // [b*L+l][cos32|sin32]
__device__ half  g_x   [(size_t)MTOK * EE];          // x fp16
__device__ half  g_wa  [(size_t)E3 * EE];            // w_attn^T  [n][k] fp16
__device__ half  g_wp  [(size_t)EE * EE];            // w_proj^T  [n][k] fp16

// ---------------------------------------------------------------------------
// helpers
// ---------------------------------------------------------------------------
__device__ __forceinline__ void mma_f16(float* c, const uint32_t* a,
                                        const uint32_t* b) {
    asm volatile(
        "mma.sync.aligned.m16n8k16.row.col.f32.f16.f16.f32 "
        "{%0,%1,%2,%3}, {%4,%5,%6,%7}, {%8,%9}, {%0,%1,%2,%3};"
        : "+f"(c[0]), "+f"(c[1]), "+f"(c[2]), "+f"(c[3])
        : "r"(a[0]), "r"(a[1]), "r"(a[2]), "r"(a[3]), "r"(b[0]), "r"(b[1]));
}

__device__ __forceinline__ void cp16(void* smem, const void* gmem) {
    uint32_t s = (uint32_t)__cvta_generic_to_shared(smem);
    asm volatile("cp.async.ca.shared.global [%0], [%1], 16;" :: "r"(s), "l"(gmem));
}
#define CP_COMMIT() asm volatile("cp.async.commit_group;" ::)
#define CP_WAIT1()  asm volatile("cp.async.wait_group 1;" ::: "memory")
#define CP_WAIT0()  asm volatile("cp.async.wait_group 0;" ::: "memory")

// ---------------------------------------------------------------------------
// fp32 -> fp16 elementwise (x)
// ---------------------------------------------------------------------------
__global__ __launch_bounds__(256) void cvt_x_kernel(const float* __restrict__ s)
{
    const int i = (blockIdx.x * blockDim.x + threadIdx.x) << 2;
    if (i >= MTOK * EE) return;
    float4 v = *(const float4*)(s + i);
    __half2 h0 = __floats2half2_rn(v.x, v.y);
    __half2 h1 = __floats2half2_rn(v.z, v.w);
    *(__half2*)(g_x + i)     = h0;
    *(__half2*)(g_x + i + 2) = h1;
}

// ---------------------------------------------------------------------------
// fp32 [K][N] -> fp16 [N][K] tiled transpose-convert (weights)
// ---------------------------------------------------------------------------
__device__ __forceinline__ void transpose_body(
    const float* __restrict__ src, half* __restrict__ dst, int K, int N)
{
    __shared__ float tile[32][33];
    const int n = blockIdx.x * 32 + threadIdx.x;
    const int k = blockIdx.y * 32 + threadIdx.y;
    #pragma unroll
    for (int j = 0; j < 32; j += 8)
        tile[threadIdx.y + j][threadIdx.x] = src[(size_t)(k + j) * N + n];
    __syncthreads();
    const int k2 = blockIdx.y * 32 + threadIdx.x;
    const int n2 = blockIdx.x * 32 + threadIdx.y;
    #pragma unroll
    for (int j = 0; j < 32; j += 8)
        dst[(size_t)(n2 + j) * K + k2] =
            __float2half_rn(tile[threadIdx.x][threadIdx.y + j]);
}
__global__ __launch_bounds__(256) void cvt_wa_kernel(const float* __restrict__ s)
{ transpose_body(s, g_wa, EE, E3); }
__global__ __launch_bounds__(256) void cvt_wp_kernel(const float* __restrict__ s)
{ transpose_body(s, g_wp, EE, EE); }

// ---------------------------------------------------------------------------
// RoPE cos/sin table
// ---------------------------------------------------------------------------
__global__ __launch_bounds__(256) void rope_table_kernel(const int* __restrict__ pos)
{
    const int i = blockIdx.x * blockDim.x + threadIdx.x;
    if (i >= BB * LL * 32) return;
    const int bl = i >> 5;
    const int j  = i & 31;
    const float p   = (float)pos[bl];
    const float inv = powf(10000.0f, -(float)j / 32.0f);
    float sn, cs;
    sincosf(p * inv, &sn, &cs);
    g_rope[(size_t)bl * 64 + j]      = cs;
    g_rope[(size_t)bl * 64 + 32 + j] = sn;
}

// ---------------------------------------------------------------------------
// fp16 cp.async double-buffered GEMM (unchanged from passing R11/R13)
// ---------------------------------------------------------------------------
#define KCH 32
#define PH  40

__device__ __forceinline__ void gemm_h(
    const half* __restrict__ A, const half* __restrict__ Wt,
    const float* __restrict__ bias, int K, int mode,
    float* __restrict__ outf)
{
    __shared__ __align__(16) half sA[2][128][PH];   // 20.5 KB
    __shared__ __align__(16) half sB[2][128][PH];   // 20.5 KB

    const int tid   = threadIdx.x;     // 0..127
    const int lane  = tid & 31;
    const int wid   = tid >> 5;        // 0..3
    const int warpM = wid & 1;
    const int warpN = wid >> 1;
    const int lq    = lane >> 2;
    const int lr    = lane & 3;

    const int m0 = blockIdx.y * 128;
    const int n0 = blockIdx.x * 128;
    const int Nn = gridDim.x * 128;

    float acc[4][8][4];
    #pragma unroll
    for (int i = 0; i < 4; i++)
        #pragma unroll
        for (int j = 0; j < 8; j++)
            #pragma unroll
            for (int c = 0; c < 4; c++) acc[i][j][c] = 0.0f;

    const int nch = K / KCH;

    {   // prefetch stage 0
        #pragma unroll
        for (int it = 0; it < 4; it++) {
            const int i   = tid + it * 128;
            const int row = i >> 2;
            const int c8  = (i & 3) << 3;
            cp16(&sA[0][row][c8], A  + (size_t)(m0 + row) * K + c8);
            cp16(&sB[0][row][c8], Wt + (size_t)(n0 + row) * K + c8);
        }
        CP_COMMIT();
    }

    for (int ch = 0; ch < nch; ch++) {
        if (ch + 1 < nch) {
            const int st = (ch + 1) & 1;
            const int k0 = (ch + 1) * KCH;
            #pragma unroll
            for (int it = 0; it < 4; it++) {
                const int i   = tid + it * 128;
                const int row = i >> 2;
                const int c8  = (i & 3) << 3;
                cp16(&sA[st][row][c8], A  + (size_t)(m0 + row) * K + k0 + c8);
                cp16(&sB[st][row][c8], Wt + (size_t)(n0 + row) * K + k0 + c8);
            }
        }
        CP_COMMIT();
        CP_WAIT1();
        __syncthreads();

        const int st = ch & 1;
        #pragma unroll
        for (int s = 0; s < 2; s++) {
            const int s16 = s * 16;
            uint32_t af[4][4], bf[8][2];
            #pragma unroll
            for (int mf = 0; mf < 4; mf++) {
                const int mr = warpM * 64 + mf * 16;
                af[mf][0] = *(const uint32_t*)&sA[st][mr + lq    ][s16 + 2*lr    ];
                af[mf][1] = *(const uint32_t*)&sA[st][mr + lq + 8][s16 + 2*lr    ];
                af[mf][2] = *(const uint32_t*)&sA[st][mr + lq    ][s16 + 2*lr + 8];
                af[mf][3] = *(const uint32_t*)&sA[st][mr + lq + 8][s16 + 2*lr + 8];
            }
            #pragma unroll
            for (int nf = 0; nf < 8; nf++) {
                const int nb = warpN * 64 + nf * 8 + lq;
                bf[nf][0] = *(const uint32_t*)&sB[st][nb][s16 + 2*lr    ];
                bf[nf][1] = *(const uint32_t*)&sB[st][nb][s16 + 2*lr + 8];
            }
            #pragma unroll
            for (int mf = 0; mf < 4; mf++)
                #pragma unroll
                for (int nf = 0; nf < 8; nf++)
                    mma_f16(acc[mf][nf], af[mf], bf[nf]);
        }
        __syncthreads();
    }

    // ---- epilogue ----
    const int gc0 = n0 + warpN * 64;
    const int q2  = lr * 2;

    float b0[8], b1[8];
    #pragma unroll
    for (int nf = 0; nf < 8; nf++) {
        b0[nf] = bias[gc0 + nf * 8 + q2];
        b1[nf] = bias[gc0 + nf * 8 + q2 + 1];
    }

    #pragma unroll
    for (int mf = 0; mf < 4; mf++) {
        #pragma unroll
        for (int rs = 0; rs < 2; rs++) {
            const int row = warpM * 64 + mf * 16 + lq + rs * 8;
            const int t   = m0 + row;
            float v[8][2];
            #pragma unroll
            for (int nf = 0; nf < 8; nf++) {
                v[nf][0] = acc[mf][nf][rs * 2]     + b0[nf];
                v[nf][1] = acc[mf][nf][rs * 2 + 1] + b1[nf];
            }
            if (mode == 0) {
                float* Crow = outf + (size_t)t * Nn + gc0;
                #pragma unroll
                for (int nf = 0; nf < 8; nf++)
                    *(float2*)(Crow + nf * 8 + q2) = make_float2(v[nf][0], v[nf][1]);
            } else if (gc0 < 1024) {
                const float* rt = g_rope +
                    (size_t)((t >> 13) * LL + ((t >> 3) & (LL - 1))) * 64;
                #pragma unroll
                for (int nf = 0; nf < 4; nf++) {
                    const int j = nf * 8 + q2;
                    const float cs0 = rt[j],     sn0 = rt[32 + j];
                    const float cs1 = rt[j + 1], sn1 = rt[33 + j];
                    const float x0 = v[nf][0], y0 = v[nf + 4][0];
                    const float x1 = v[nf][1], y1 = v[nf + 4][1];
                    v[nf][0]     = x0 * cs0 - y0 * sn0;
                    v[nf + 4][0] = y0 * cs0 + x0 * sn0;
                    v[nf][1]     = x1 * cs1 - y1 * sn1;
                    v[nf + 4][1] = y1 * cs1 + x1 * sn1;
                }
                half* Crow = g_qkv + (size_t)t * 1024 + gc0;
                #pragma unroll
                for (int nf = 0; nf < 8; nf++)
                    *(__half2*)(Crow + nf * 8 + q2) =
                        __floats2half2_rn(v[nf][0], v[nf][1]);
            } else {
                const int bb_ = t >> 13;
                const int nn_ = t & 7;
                const int ll_ = (t >> 3) & (LL - 1);
                #pragma unroll
                for (int nf = 0; nf < 8; nf++) {
                    const int dg = gc0 + nf * 8 + q2 - 1024;
                    const int h_ = dg >> 6;
                    const int d_ = dg & 63;
                    const size_t base =
                        (((size_t)((bb_ * NN + nn_) * HH + h_) * HD) + d_) * LL + ll_;
                    g_v[base]      = __float2half_rn(v[nf][0]);
                    g_v[base + LL] = __float2half_rn(v[nf][1]);
                }
            }
        }
    }
}

__global__ __launch_bounds__(128) void qkv_mma_kernel(const float* __restrict__ b_attn)
{
    gemm_h(g_x, g_wa, b_attn, EE, 1, (float*)0);
}

__global__ __launch_bounds__(128) void proj_mma_kernel(
    const float* __restrict__ b_proj, float* __restrict__ out)
{
    gemm_h(g_y, g_wp, b_proj, EE, 0, out);
}

// ---------------------------------------------------------------------------
// Flash attention, fp16 m16n8k16, BQ=64 (4 warps), double-buffered K/V.
// R14 deltas: exp2-domain softmax (scale folded with log2e); reversed qt
// order so longest CTAs launch first (tail packing).
// ---------------------------------------------------------------------------
#define AKV 64
#define PAH 72
#define SCALE2 0.18033688f   // (1/8) * log2(e)

__global__ __launch_bounds__(128) void attn_mma_kernel()
{
    __shared__ __align__(16) half sQP[64][PAH];      // Q staging, then P
    __shared__ __align__(16) half sK [2][AKV][PAH];  // K  [kv][hd], 2 stages
    __shared__ __align__(16) half sVt[2][HD][PAH];   // V^T [d][kv], 2 stages

    const int bnh  = blockIdx.y;
    const int h    = bnh & 7;
    const int n    = (bnh >> 3) & 7;
    const int b    = bnh >> 6;
    const int qt   = (gridDim.x - 1) - blockIdx.x;   // longest CTAs first

    const int tid  = threadIdx.x;
    const int lane = tid & 31;
    const int wid  = tid >> 5;
    const int lq   = lane >> 2;
    const int lr   = lane & 3;
    const int w16  = wid * 16;

    const size_t vbase = (size_t)bnh * HD * LL;

    // ---- stage Q (group 0) ----
    #pragma unroll
    for (int it = 0; it < 4; it++) {
        const int i  = tid + it * 128;      // 0..511
        const int r  = i >> 3;
        const int c8 = (i & 7) << 3;
        cp16(&sQP[r][c8],
             g_qkv + (size_t)((b * LL + qt * 64 + r) * NN + n) * 1024 + h * HD + c8);
    }
    CP_COMMIT();

    // ---- prefetch kv tile 0 into stage 0 (group 1) ----
    #pragma unroll
    for (int it = 0; it < 4; it++) {
        const int i  = tid + it * 128;
        const int r  = i >> 3;
        const int c8 = (i & 7) << 3;
        cp16(&sK[0][r][c8],
             g_qkv + (size_t)((b * LL + r) * NN + n) * 1024 + 512 + h * HD + c8);
        cp16(&sVt[0][r][c8], g_v + vbase + (size_t)r * LL + c8);
    }
    CP_COMMIT();

    CP_WAIT1();        // Q resident (kv0 may still be in flight)
    __syncthreads();

    // ---- preload Q fragments ----
    uint32_t aq[4][4];
    #pragma unroll
    for (int ks = 0; ks < 4; ks++) {
        const int k0 = ks * 16;
        aq[ks][0] = *(const uint32_t*)&sQP[w16 + lq    ][k0 + 2*lr    ];
        aq[ks][1] = *(const uint32_t*)&sQP[w16 + lq + 8][k0 + 2*lr    ];
        aq[ks][2] = *(const uint32_t*)&sQP[w16 + lq    ][k0 + 2*lr + 8];
        aq[ks][3] = *(const uint32_t*)&sQP[w16 + lq + 8][k0 + 2*lr + 8];
    }

    float m_run[2] = {-1e30f, -1e30f};
    float l_run[2] = {0.0f, 0.0f};
    float acc[8][4];
    #pragma unroll
    for (int nf = 0; nf < 8; nf++)
        #pragma unroll
        for (int c = 0; c < 4; c++) acc[nf][c] = 0.0f;

    const int nT = qt + 1;
    for (int kt = 0; kt < nT; kt++) {
        // ---- prefetch tile kt+1 into stage (kt+1)&1 ----
        if (kt + 1 < nT) {
            const int st = (kt + 1) & 1;
            #pragma unroll
            for (int it = 0; it < 4; it++) {
                const int i  = tid + it * 128;
                const int r  = i >> 3;
                const int c8 = (i & 7) << 3;
                cp16(&sK[st][r][c8],
                     g_qkv + (size_t)((b * LL + (kt + 1) * AKV + r) * NN + n) * 1024
                           + 512 + h * HD + c8);
                cp16(&sVt[st][r][c8],
                     g_v + vbase + (size_t)r * LL + (kt + 1) * AKV + c8);
            }
        }
        CP_COMMIT();
        CP_WAIT1();        // tile kt resident; kt+1 in flight
        __syncthreads();

        const int st = kt & 1;

        // ---- S = Q K^T  (32 mma) ----
        float s[8][4];
        #pragma unroll
        for (int nf = 0; nf < 8; nf++)
            #pragma unroll
            for (int c = 0; c < 4; c++) s[nf][c] = 0.0f;

        #pragma unroll
        for (int ks = 0; ks < 4; ks++) {
            const int k0 = ks * 16;
            #pragma unroll
            for (int nf = 0; nf < 8; nf++) {
                uint32_t bb[2];
                bb[0] = *(const uint32_t*)&sK[st][nf * 8 + lq][k0 + 2*lr    ];
                bb[1] = *(const uint32_t*)&sK[st][nf * 8 + lq][k0 + 2*lr + 8];
                mma_f16(s[nf], aq[ks], bb);
            }
        }

        // ---- scale (exp2 domain) + causal mask + online softmax ----
        const bool diag = (kt == qt);
        const int  r0l  = w16 + lq;
        const int  r1l  = r0l + 8;
        float mx0 = -1e30f, mx1 = -1e30f;
        #pragma unroll
        for (int nf = 0; nf < 8; nf++) {
            #pragma unroll
            for (int c = 0; c < 2; c++) {
                const int col = nf * 8 + 2 * lr + c;
                float v0 = s[nf][c]     * SCALE2;
                float v1 = s[nf][2 + c] * SCALE2;
                if (diag && col > r0l) v0 = -1e30f;
                if (diag && col > r1l) v1 = -1e30f;
                s[nf][c]     = v0;
                s[nf][2 + c] = v1;
                mx0 = fmaxf(mx0, v0);
                mx1 = fmaxf(mx1, v1);
            }
        }
        #pragma unroll
        for (int off = 1; off < 4; off <<= 1) {
            mx0 = fmaxf(mx0, __shfl_xor_sync(0xffffffffu, mx0, off));
            mx1 = fmaxf(mx1, __shfl_xor_sync(0xffffffffu, mx1, off));
        }

        const float mn0 = fmaxf(m_run[0], mx0);
        const float mn1 = fmaxf(m_run[1], mx1);
        const float al0 = exp2f(m_run[0] - mn0);
        const float al1 = exp2f(m_run[1] - mn1);
        m_run[0] = mn0; m_run[1] = mn1;

        float sum0 = 0.0f, sum1 = 0.0f;
        #pragma unroll
        for (int nf = 0; nf < 8; nf++) {
            const float p00 = exp2f(s[nf][0] - mn0);
            const float p01 = exp2f(s[nf][1] - mn0);
            const float p10 = exp2f(s[nf][2] - mn1);
            const float p11 = exp2f(s[nf][3] - mn1);
            sum0 += p00 + p01;
            sum1 += p10 + p11;
            const int cc = nf * 8 + 2 * lr;
            *(__half2*)&sQP[r0l][cc] = __floats2half2_rn(p00, p01);
            *(__half2*)&sQP[r1l][cc] = __floats2half2_rn(p10, p11);
        }
        #pragma unroll
        for (int off = 1; off < 4; off <<= 1) {
            sum0 += __shfl_xor_sync(0xffffffffu, sum0, off);
            sum1 += __shfl_xor_sync(0xffffffffu, sum1, off);
        }
        l_run[0] = l_run[0] * al0 + sum0;
        l_run[1] = l_run[1] * al1 + sum1;

        #pragma unroll
        for (int nf = 0; nf < 8; nf++) {
            acc[nf][0] *= al0; acc[nf][1] *= al0;
            acc[nf][2] *= al1; acc[nf][3] *= al1;
        }
        __syncwarp();      // P rows warp-private

        // ---- O += P V  (32 mma) ----
        #pragma unroll
        for (int ks = 0; ks < 4; ks++) {
            const int k0 = ks * 16;
            uint32_t ap[4];
            ap[0] = *(const uint32_t*)&sQP[r0l][k0 + 2*lr    ];
            ap[1] = *(const uint32_t*)&sQP[r1l][k0 + 2*lr    ];
            ap[2] = *(const uint32_t*)&sQP[r0l][k0 + 2*lr + 8];
            ap[3] = *(const uint32_t*)&sQP[r1l][k0 + 2*lr + 8];
            #pragma unroll
            for (int nf = 0; nf < 8; nf++) {
                uint32_t bb[2];
                bb[0] = *(const uint32_t*)&sVt[st][nf * 8 + lq][k0 + 2*lr    ];
                bb[1] = *(const uint32_t*)&sVt[st][nf * 8 + lq][k0 + 2*lr + 8];
                mma_f16(acc[nf], ap, bb);
            }
        }
        __syncthreads();   // stage st free for the prefetch in iteration kt+1
    }

    // ---- epilogue: normalize + half store to g_y ----
    const float inv0 = 1.0f / l_run[0];
    const float inv1 = 1.0f / l_run[1];
    const int gr0 = qt * 64 + w16 + lq;
    const int gr1 = gr0 + 8;
    half* y0 = g_y + (size_t)((b * LL + gr0) * NN + n) * EE + h * HD;
    half* y1 = g_y + (size_t)((b * LL + gr1) * NN + n) * EE + h * HD;
    #pragma unroll
    for (int nf = 0; nf < 8; nf++) {
        const int cc = nf * 8 + 2 * lr;
        *(__half2*)(y0 + cc) = __floats2half2_rn(acc[nf][0] * inv0,
                                                 acc[nf][1] * inv0);
        *(__half2*)(y1 + cc) = __floats2half2_rn(acc[nf][2] * inv1,
                                                 acc[nf][3] * inv1);
    }
}

// ---------------------------------------------------------------------------
// launch
// ---------------------------------------------------------------------------
extern "C" void kernel_launch(void* const* d_in, const int* in_sizes, int n_in,
                              void* d_out, int out_size)
{
    const float* x      = (const float*)d_in[0];
    const int*   pos    = (const int*)  d_in[1];
    const float* w_attn = (const float*)d_in[2];
    const float* b_attn = (const float*)d_in[3];
    const float* w_proj = (const float*)d_in[4];
    const float* b_proj = (const float*)d_in[5];
    float*       out    = (float*)d_out;

    // 0) convert x -> fp16; transpose-convert weights -> [n][k] fp16
    cvt_x_kernel<<<(MTOK * EE / 4 + 255) / 256, 256>>>(x);
    cvt_wa_kernel<<<dim3(E3 / 32, EE / 32), dim3(32, 8)>>>(w_attn);
    cvt_wp_kernel<<<dim3(EE / 32, EE / 32), dim3(32, 8)>>>(w_proj);

    // 1) cos/sin table
    rope_table_kernel<<<(BB * LL * 32) / 256, 256>>>(pos);

    // 2) QKV fp16 GEMM + fused bias + RoPE; V stored transposed
    qkv_mma_kernel<<<dim3(E3 / 128, MTOK / 128), 128>>>(b_attn);

    // 3) causal flash attention (fp16, BQ=64, 2-stage K/V, exp2 softmax)
    attn_mma_kernel<<<dim3(LL / 64, BB * NN * HH), 128>>>();

    // 4) out = y @ w_proj + b_proj (fp32 store)
    proj_mma_kernel<<<dim3(EE / 128, MTOK / 128), 128>>>(b_proj, out);
}

// round 15
// speedup vs baseline: 1.1029x; 1.0562x over previous
#include <cuda_runtime.h>
#include <cuda_fp16.h>
#include <math.h>
#include <stdint.h>

// Problem dims (fixed by the dataset)
#define BB    2
#define LL    1024
#define NN    8
#define EE    512
#define HH    8
#define HD    64
#define E3    1536
#define MTOK  (BB * LL * NN)          // 16384 tokens

// ---------------------------------------------------------------------------
// Scratch (device globals)
// ---------------------------------------------------------------------------
__device__ half  g_qkv [(size_t)MTOK * 1024];        // [token][1024] q|k post-RoPE
__device__ half  g_v   [(size_t)BB * NN * HH * HD * LL]; // [bnh][d][L] V transposed
__device__ half  g_y   [(size_t)MTOK * EE];          // attention out
__device__ float g_rope[(size_t)BB * LL * 64];       // [b*L+l][cos32|sin32]
__device__ half  g_x   [(size_t)MTOK * EE];          // x fp16
__device__ half  g_wa  [(size_t)E3 * EE];            // w_attn^T  [n][k] fp16
__device__ half  g_wp  [(size_t)EE * EE];            // w_proj^T  [n][k] fp16

// ---------------------------------------------------------------------------
// helpers
// ---------------------------------------------------------------------------
__device__ __forceinline__ void mma_f16(float* c, const uint32_t* a,
                                        const uint32_t* b) {
    asm volatile(
        "mma.sync.aligned.m16n8k16.row.col.f32.f16.f16.f32 "
        "{%0,%1,%2,%3}, {%4,%5,%6,%7}, {%8,%9}, {%0,%1,%2,%3};"
        : "+f"(c[0]), "+f"(c[1]), "+f"(c[2]), "+f"(c[3])
        : "r"(a[0]), "r"(a[1]), "r"(a[2]), "r"(a[3]), "r"(b[0]), "r"(b[1]));
}

__device__ __forceinline__ void cp16(void* smem, const void* gmem) {
    uint32_t s = (uint32_t)__cvta_generic_to_shared(smem);
    asm volatile("cp.async.ca.shared.global [%0], [%1], 16;" :: "r"(s), "l"(gmem));
}
#define CP_COMMIT() asm volatile("cp.async.commit_group;" ::)
#define CP_WAIT1()  asm volatile("cp.async.wait_group 1;" ::: "memory")
#define CP_WAIT0()  asm volatile("cp.async.wait_group 0;" ::: "memory")

__device__ __forceinline__ void ldsm_x4(uint32_t& r0, uint32_t& r1,
                                        uint32_t& r2, uint32_t& r3,
                                        const void* p) {
    uint32_t a = (uint32_t)__cvta_generic_to_shared(p);
    asm volatile("ldmatrix.sync.aligned.m8n8.x4.shared.b16 {%0,%1,%2,%3}, [%4];"
                 : "=r"(r0), "=r"(r1), "=r"(r2), "=r"(r3) : "r"(a));
}

// ---------------------------------------------------------------------------
// fp32 -> fp16 elementwise (x)
// ---------------------------------------------------------------------------
__global__ __launch_bounds__(256) void cvt_x_kernel(const float* __restrict__ s)
{
    const int i = (blockIdx.x * blockDim.x + threadIdx.x) << 2;
    if (i >= MTOK * EE) return;
    float4 v = *(const float4*)(s + i);
    __half2 h0 = __floats2half2_rn(v.x, v.y);
    __half2 h1 = __floats2half2_rn(v.z, v.w);
    *(__half2*)(g_x + i)     = h0;
    *(__half2*)(g_x + i + 2) = h1;
}

// ---------------------------------------------------------------------------
// fp32 [K][N] -> fp16 [N][K] tiled transpose-convert (weights)
// ---------------------------------------------------------------------------
__device__ __forceinline__ void transpose_body(
    const float* __restrict__ src, half* __restrict__ dst, int K, int N)
{
    __shared__ float tile[32][33];
    const int n = blockIdx.x * 32 + threadIdx.x;
    const int k = blockIdx.y * 32 + threadIdx.y;
    #pragma unroll
    for (int j = 0; j < 32; j += 8)
        tile[threadIdx.y + j][threadIdx.x] = src[(size_t)(k + j) * N + n];
    __syncthreads();
    const int k2 = blockIdx.y * 32 + threadIdx.x;
    const int n2 = blockIdx.x * 32 + threadIdx.y;
    #pragma unroll
    for (int j = 0; j < 32; j += 8)
        dst[(size_t)(n2 + j) * K + k2] =
            __float2half_rn(tile[threadIdx.x][threadIdx.y + j]);
}
__global__ __launch_bounds__(256) void cvt_wa_kernel(const float* __restrict__ s)
{ transpose_body(s, g_wa, EE, E3); }
__global__ __launch_bounds__(256) void cvt_wp_kernel(const float* __restrict__ s)
{ transpose_body(s, g_wp, EE, EE); }

// ---------------------------------------------------------------------------
// RoPE cos/sin table
// ---------------------------------------------------------------------------
__global__ __launch_bounds__(256) void rope_table_kernel(const int* __restrict__ pos)
{
    const int i = blockIdx.x * blockDim.x + threadIdx.x;
    if (i >= BB * LL * 32) return;
    const int bl = i >> 5;
    const int j  = i & 31;
    const float p   = (float)pos[bl];
    const float inv = powf(10000.0f, -(float)j / 32.0f);
    float sn, cs;
    sincosf(p * inv, &sn, &cs);
    g_rope[(size_t)bl * 64 + j]      = cs;
    g_rope[(size_t)bl * 64 + 32 + j] = sn;
}

// ---------------------------------------------------------------------------
// fp16 cp.async double-buffered GEMM, ldmatrix fragment loads.
// 128 thr = 4 warps (2M x 2N), warp tile 64x64, KC=32/stage.
// ---------------------------------------------------------------------------
#define KCH 32
#define PH  40

__device__ __forceinline__ void gemm_h(
    const half* __restrict__ A, const half* __restrict__ Wt,
    const float* __restrict__ bias, int K, int mode,
    float* __restrict__ outf)
{
    __shared__ __align__(16) half sA[2][128][PH];   // 20.5 KB
    __shared__ __align__(16) half sB[2][128][PH];   // 20.5 KB

    const int tid   = threadIdx.x;     // 0..127
    const int lane  = tid & 31;
    const int wid   = tid >> 5;        // 0..3
    const int warpM = wid & 1;
    const int warpN = wid >> 1;
    const int lq    = lane >> 2;
    const int lr    = lane & 3;

    // ldmatrix lane mapping
    const int lrow = lane & 7;
    const int lg1  = (lane >> 3) & 1;   // +8 rows (A) / k-half (B)
    const int lg2  = lane >> 4;         // k-half (A) / +8 rows = next frag (B)

    const int m0 = blockIdx.y * 128;
    const int n0 = blockIdx.x * 128;
    const int Nn = gridDim.x * 128;

    float acc[4][8][4];
    #pragma unroll
    for (int i = 0; i < 4; i++)
        #pragma unroll
        for (int j = 0; j < 8; j++)
            #pragma unroll
            for (int c = 0; c < 4; c++) acc[i][j][c] = 0.0f;

    const int nch = K / KCH;

    {   // prefetch stage 0
        #pragma unroll
        for (int it = 0; it < 4; it++) {
            const int i   = tid + it * 128;
            const int row = i >> 2;
            const int c8  = (i & 3) << 3;
            cp16(&sA[0][row][c8], A  + (size_t)(m0 + row) * K + c8);
            cp16(&sB[0][row][c8], Wt + (size_t)(n0 + row) * K + c8);
        }
        CP_COMMIT();
    }

    for (int ch = 0; ch < nch; ch++) {
        if (ch + 1 < nch) {
            const int st = (ch + 1) & 1;
            const int k0 = (ch + 1) * KCH;
            #pragma unroll
            for (int it = 0; it < 4; it++) {
                const int i   = tid + it * 128;
                const int row = i >> 2;
                const int c8  = (i & 3) << 3;
                cp16(&sA[st][row][c8], A  + (size_t)(m0 + row) * K + k0 + c8);
                cp16(&sB[st][row][c8], Wt + (size_t)(n0 + row) * K + k0 + c8);
            }
        }
        CP_COMMIT();
        CP_WAIT1();
        __syncthreads();

        const int st = ch & 1;
        #pragma unroll
        for (int s = 0; s < 2; s++) {
            const int s16 = s * 16;
            uint32_t af[4][4], bf[8][2];
            // A frags: one ldsm.x4 per mf
            #pragma unroll
            for (int mf = 0; mf < 4; mf++) {
                const int mr = warpM * 64 + mf * 16;
                ldsm_x4(af[mf][0], af[mf][1], af[mf][2], af[mf][3],
                        &sA[st][mr + lrow + lg1 * 8][s16 + lg2 * 8]);
            }
            // B frags: one ldsm.x4 per nf pair
            #pragma unroll
            for (int np = 0; np < 4; np++) {
                const int nb = warpN * 64 + np * 16;
                ldsm_x4(bf[np*2][0], bf[np*2][1], bf[np*2+1][0], bf[np*2+1][1],
                        &sB[st][nb + lrow + lg2 * 8][s16 + lg1 * 8]);
            }
            #pragma unroll
            for (int mf = 0; mf < 4; mf++)
                #pragma unroll
                for (int nf = 0; nf < 8; nf++)
                    mma_f16(acc[mf][nf], af[mf], bf[nf]);
        }
        __syncthreads();
    }

    // ---- epilogue ----
    const int gc0 = n0 + warpN * 64;
    const int q2  = lr * 2;

    float b0[8], b1[8];
    #pragma unroll
    for (int nf = 0; nf < 8; nf++) {
        b0[nf] = bias[gc0 + nf * 8 + q2];
        b1[nf] = bias[gc0 + nf * 8 + q2 + 1];
    }

    #pragma unroll
    for (int mf = 0; mf < 4; mf++) {
        #pragma unroll
        for (int rs = 0; rs < 2; rs++) {
            const int row = warpM * 64 + mf * 16 + lq + rs * 8;
            const int t   = m0 + row;
            float v[8][2];
            #pragma unroll
            for (int nf = 0; nf < 8; nf++) {
                v[nf][0] = acc[mf][nf][rs * 2]     + b0[nf];
                v[nf][1] = acc[mf][nf][rs * 2 + 1] + b1[nf];
            }
            if (mode == 0) {
                float* Crow = outf + (size_t)t * Nn + gc0;
                #pragma unroll
                for (int nf = 0; nf < 8; nf++)
                    *(float2*)(Crow + nf * 8 + q2) = make_float2(v[nf][0], v[nf][1]);
            } else if (gc0 < 1024) {
                const float* rt = g_rope +
                    (size_t)((t >> 13) * LL + ((t >> 3) & (LL - 1))) * 64;
                #pragma unroll
                for (int nf = 0; nf < 4; nf++) {
                    const int j = nf * 8 + q2;
                    const float cs0 = rt[j],     sn0 = rt[32 + j];
                    const float cs1 = rt[j + 1], sn1 = rt[33 + j];
                    const float x0 = v[nf][0], y0 = v[nf + 4][0];
                    const float x1 = v[nf][1], y1 = v[nf + 4][1];
                    v[nf][0]     = x0 * cs0 - y0 * sn0;
                    v[nf + 4][0] = y0 * cs0 + x0 * sn0;
                    v[nf][1]     = x1 * cs1 - y1 * sn1;
                    v[nf + 4][1] = y1 * cs1 + x1 * sn1;
                }
                half* Crow = g_qkv + (size_t)t * 1024 + gc0;
                #pragma unroll
                for (int nf = 0; nf < 8; nf++)
                    *(__half2*)(Crow + nf * 8 + q2) =
                        __floats2half2_rn(v[nf][0], v[nf][1]);
            } else {
                const int bb_ = t >> 13;
                const int nn_ = t & 7;
                const int ll_ = (t >> 3) & (LL - 1);
                #pragma unroll
                for (int nf = 0; nf < 8; nf++) {
                    const int dg = gc0 + nf * 8 + q2 - 1024;
                    const int h_ = dg >> 6;
                    const int d_ = dg & 63;
                    const size_t base =
                        (((size_t)((bb_ * NN + nn_) * HH + h_) * HD) + d_) * LL + ll_;
                    g_v[base]      = __float2half_rn(v[nf][0]);
                    g_v[base + LL] = __float2half_rn(v[nf][1]);
                }
            }
        }
    }
}

__global__ __launch_bounds__(128) void qkv_mma_kernel(const float* __restrict__ b_attn)
{
    gemm_h(g_x, g_wa, b_attn, EE, 1, (float*)0);
}

__global__ __launch_bounds__(128) void proj_mma_kernel(
    const float* __restrict__ b_proj, float* __restrict__ out)
{
    gemm_h(g_y, g_wp, b_proj, EE, 0, out);
}

// ---------------------------------------------------------------------------
// Flash attention, fp16 m16n8k16, BQ=64 (4 warps), double-buffered K/V,
// exp2 softmax, reversed qt order, ldmatrix fragment loads.
// ---------------------------------------------------------------------------
#define AKV 64
#define PAH 72
#define SCALE2 0.18033688f   // (1/8) * log2(e)

__global__ __launch_bounds__(128) void attn_mma_kernel()
{
    __shared__ __align__(16) half sQP[64][PAH];      // Q staging, then P
    __shared__ __align__(16) half sK [2][AKV][PAH];  // K  [kv][hd], 2 stages
    __shared__ __align__(16) half sVt[2][HD][PAH];   // V^T [d][kv], 2 stages

    const int bnh  = blockIdx.y;
    const int h    = bnh & 7;
    const int n    = (bnh >> 3) & 7;
    const int b    = bnh >> 6;
    const int qt   = (gridDim.x - 1) - blockIdx.x;   // longest CTAs first

    const int tid  = threadIdx.x;
    const int lane = tid & 31;
    const int wid  = tid >> 5;
    const int lq   = lane >> 2;
    const int lr   = lane & 3;
    const int w16  = wid * 16;

    const int lrow = lane & 7;
    const int lg1  = (lane >> 3) & 1;
    const int lg2  = lane >> 4;

    const size_t vbase = (size_t)bnh * HD * LL;

    // ---- stage Q (group 0) ----
    #pragma unroll
    for (int it = 0; it < 4; it++) {
        const int i  = tid + it * 128;      // 0..511
        const int r  = i >> 3;
        const int c8 = (i & 7) << 3;
        cp16(&sQP[r][c8],
             g_qkv + (size_t)((b * LL + qt * 64 + r) * NN + n) * 1024 + h * HD + c8);
    }
    CP_COMMIT();

    // ---- prefetch kv tile 0 into stage 0 (group 1) ----
    #pragma unroll
    for (int it = 0; it < 4; it++) {
        const int i  = tid + it * 128;
        const int r  = i >> 3;
        const int c8 = (i & 7) << 3;
        cp16(&sK[0][r][c8],
             g_qkv + (size_t)((b * LL + r) * NN + n) * 1024 + 512 + h * HD + c8);
        cp16(&sVt[0][r][c8], g_v + vbase + (size_t)r * LL + c8);
    }
    CP_COMMIT();

    CP_WAIT1();        // Q resident (kv0 may still be in flight)
    __syncthreads();

    // ---- preload Q fragments (ldmatrix) ----
    uint32_t aq[4][4];
    #pragma unroll
    for (int ks = 0; ks < 4; ks++) {
        ldsm_x4(aq[ks][0], aq[ks][1], aq[ks][2], aq[ks][3],
                &sQP[w16 + lrow + lg1 * 8][ks * 16 + lg2 * 8]);
    }

    float m_run[2] = {-1e30f, -1e30f};
    float l_run[2] = {0.0f, 0.0f};
    float acc[8][4];
    #pragma unroll
    for (int nf = 0; nf < 8; nf++)
        #pragma unroll
        for (int c = 0; c < 4; c++) acc[nf][c] = 0.0f;

    const int nT = qt + 1;
    for (int kt = 0; kt < nT; kt++) {
        // ---- prefetch tile kt+1 into stage (kt+1)&1 ----
        if (kt + 1 < nT) {
            const int st = (kt + 1) & 1;
            #pragma unroll
            for (int it = 0; it < 4; it++) {
                const int i  = tid + it * 128;
                const int r  = i >> 3;
                const int c8 = (i & 7) << 3;
                cp16(&sK[st][r][c8],
                     g_qkv + (size_t)((b * LL + (kt + 1) * AKV + r) * NN + n) * 1024
                           + 512 + h * HD + c8);
                cp16(&sVt[st][r][c8],
                     g_v + vbase + (size_t)r * LL + (kt + 1) * AKV + c8);
            }
        }
        CP_COMMIT();
        CP_WAIT1();        // tile kt resident; kt+1 in flight
        __syncthreads();

        const int st = kt & 1;

        // ---- S = Q K^T  (32 mma; B frags via ldsm.x4 per nf pair) ----
        float s[8][4];
        #pragma unroll
        for (int nf = 0; nf < 8; nf++)
            #pragma unroll
            for (int c = 0; c < 4; c++) s[nf][c] = 0.0f;

        #pragma unroll
        for (int ks = 0; ks < 4; ks++) {
            const int k0 = ks * 16;
            uint32_t bk[8][2];
            #pragma unroll
            for (int np = 0; np < 4; np++) {
                ldsm_x4(bk[np*2][0], bk[np*2][1], bk[np*2+1][0], bk[np*2+1][1],
                        &sK[st][np * 16 + lrow + lg2 * 8][k0 + lg1 * 8]);
            }
            #pragma unroll
            for (int nf = 0; nf < 8; nf++)
                mma_f16(s[nf], aq[ks], bk[nf]);
        }

        // ---- scale (exp2 domain) + causal mask + online softmax ----
        const bool diag = (kt == qt);
        const int  r0l  = w16 + lq;
        const int  r1l  = r0l + 8;
        float mx0 = -1e30f, mx1 = -1e30f;
        #pragma unroll
        for (int nf = 0; nf < 8; nf++) {
            #pragma unroll
            for (int c = 0; c < 2; c++) {
                const int col = nf * 8 + 2 * lr + c;
                float v0 = s[nf][c]     * SCALE2;
                float v1 = s[nf][2 + c] * SCALE2;
                if (diag && col > r0l) v0 = -1e30f;
                if (diag && col > r1l) v1 = -1e30f;
                s[nf][c]     = v0;
                s[nf][2 + c] = v1;
                mx0 = fmaxf(mx0, v0);
                mx1 = fmaxf(mx1, v1);
            }
        }
        #pragma unroll
        for (int off = 1; off < 4; off <<= 1) {
            mx0 = fmaxf(mx0, __shfl_xor_sync(0xffffffffu, mx0, off));
            mx1 = fmaxf(mx1, __shfl_xor_sync(0xffffffffu, mx1, off));
        }

        const float mn0 = fmaxf(m_run[0], mx0);
        const float mn1 = fmaxf(m_run[1], mx1);
        const float al0 = exp2f(m_run[0] - mn0);
        const float al1 = exp2f(m_run[1] - mn1);
        m_run[0] = mn0; m_run[1] = mn1;

        float sum0 = 0.0f, sum1 = 0.0f;
        #pragma unroll
        for (int nf = 0; nf < 8; nf++) {
            const float p00 = exp2f(s[nf][0] - mn0);
            const float p01 = exp2f(s[nf][1] - mn0);
            const float p10 = exp2f(s[nf][2] - mn1);
            const float p11 = exp2f(s[nf][3] - mn1);
            sum0 += p00 + p01;
            sum1 += p10 + p11;
            const int cc = nf * 8 + 2 * lr;
            *(__half2*)&sQP[r0l][cc] = __floats2half2_rn(p00, p01);
            *(__half2*)&sQP[r1l][cc] = __floats2half2_rn(p10, p11);
        }
        #pragma unroll
        for (int off = 1; off < 4; off <<= 1) {
            sum0 += __shfl_xor_sync(0xffffffffu, sum0, off);
            sum1 += __shfl_xor_sync(0xffffffffu, sum1, off);
        }
        l_run[0] = l_run[0] * al0 + sum0;
        l_run[1] = l_run[1] * al1 + sum1;

        #pragma unroll
        for (int nf = 0; nf < 8; nf++) {
            acc[nf][0] *= al0; acc[nf][1] *= al0;
            acc[nf][2] *= al1; acc[nf][3] *= al1;
        }
        __syncwarp();      // P rows warp-private

        // ---- O += P V  (32 mma; P a-frags + V b-frags via ldmatrix) ----
        #pragma unroll
        for (int ks = 0; ks < 4; ks++) {
            const int k0 = ks * 16;
            uint32_t ap[4];
            ldsm_x4(ap[0], ap[1], ap[2], ap[3],
                    &sQP[w16 + lrow + lg1 * 8][k0 + lg2 * 8]);
            uint32_t bv[8][2];
            #pragma unroll
            for (int np = 0; np < 4; np++) {
                ldsm_x4(bv[np*2][0], bv[np*2][1], bv[np*2+1][0], bv[np*2+1][1],
                        &sVt[st][np * 16 + lrow + lg2 * 8][k0 + lg1 * 8]);
            }
            #pragma unroll
            for (int nf = 0; nf < 8; nf++)
                mma_f16(acc[nf], ap, bv[nf]);
        }
        __syncthreads();   // stage st free for the prefetch in iteration kt+1
    }

    // ---- epilogue: normalize + half store to g_y ----
    const float inv0 = 1.0f / l_run[0];
    const float inv1 = 1.0f / l_run[1];
    const int gr0 = qt * 64 + w16 + lq;
    const int gr1 = gr0 + 8;
    half* y0 = g_y + (size_t)((b * LL + gr0) * NN + n) * EE + h * HD;
    half* y1 = g_y + (size_t)((b * LL + gr1) * NN + n) * EE + h * HD;
    #pragma unroll
    for (int nf = 0; nf < 8; nf++) {
        const int cc = nf * 8 + 2 * lr;
        *(__half2*)(y0 + cc) = __floats2half2_rn(acc[nf][0] * inv0,
                                                 acc[nf][1] * inv0);
        *(__half2*)(y1 + cc) = __floats2half2_rn(acc[nf][2] * inv1,
                                                 acc[nf][3] * inv1);
    }
}

// ---------------------------------------------------------------------------
// launch
// ---------------------------------------------------------------------------
extern "C" void kernel_launch(void* const* d_in, const int* in_sizes, int n_in,
                              void* d_out, int out_size)
{
    const float* x      = (const float*)d_in[0];
    const int*   pos    = (const int*)  d_in[1];
    const float* w_attn = (const float*)d_in[2];
    const float* b_attn = (const float*)d_in[3];
    const float* w_proj = (const float*)d_in[4];
    const float* b_proj = (const float*)d_in[5];
    float*       out    = (float*)d_out;

    // 0) convert x -> fp16; transpose-convert weights -> [n][k] fp16
    cvt_x_kernel<<<(MTOK * EE / 4 + 255) / 256, 256>>>(x);
    cvt_wa_kernel<<<dim3(E3 / 32, EE / 32), dim3(32, 8)>>>(w_attn);
    cvt_wp_kernel<<<dim3(EE / 32, EE / 32), dim3(32, 8)>>>(w_proj);

    // 1) cos/sin table
    rope_table_kernel<<<(BB * LL * 32) / 256, 256>>>(pos);

    // 2) QKV fp16 GEMM + fused bias + RoPE; V stored transposed
    qkv_mma_kernel<<<dim3(E3 / 128, MTOK / 128), 128>>>(b_attn);

    // 3) causal flash attention (fp16, ldmatrix, 2-stage K/V, exp2 softmax)
    attn_mma_kernel<<<dim3(LL / 64, BB * NN * HH), 128>>>();

    // 4) out = y @ w_proj + b_proj (fp32 store)
    proj_mma_kernel<<<dim3(EE / 128, MTOK / 128), 128>>>(b_proj, out);
}